// round 16
// baseline (speedup 1.0000x reference)
#include <cuda_runtime.h>
#include <cuda_fp16.h>
#include <math.h>
#include <stdint.h>

// Problem constants
#define B_    16
#define HH    56
#define WW_   56
#define C_    512
#define NH_   16
#define WS_   7
#define SS_   3
#define NTOK  49
#define NWIN  64
#define HD_   32
#define MLPH  2048
#define MROWS 50176
#define SCALE_ 0.17677669529663687f

// ---------------- scratch ----------------------------------------------------
__device__ __half g_a1w [(size_t)MROWS * 512];
__device__ __half g_qkv [(size_t)MROWS * 1536];
__device__ __half g_attn[(size_t)MROWS * 512];
__device__ float  g_x   [(size_t)MROWS * 512];
__device__ __half g_ln2 [(size_t)MROWS * 512];
__device__ __half g_h1  [(size_t)MROWS * 2048];
__device__ __half g_wq [1536 * 512];
__device__ __half g_wp [512 * 512];
__device__ __half g_w1 [2048 * 512];
__device__ __half g_w2 [512 * 2048];
__device__ float  g_bias[4 * 16 * NTOK * NTOK];   // precomputed bias+mask per class/head

__global__ __launch_bounds__(256)
void round_kernel(const float* __restrict__ src, __half* __restrict__ dst, int n)
{
    int i = blockIdx.x * 1024 + threadIdx.x * 4;
    if (i < n) {
        float4 v = *(const float4*)(src + i);
        *(__half2*)(dst + i)     = __floats2half2_rn(v.x, v.y);
        *(__half2*)(dst + i + 2) = __floats2half2_rn(v.z, v.w);
    }
}

// precompute bias + shifted-window mask: blockIdx.x = cls*16 + h
__global__ __launch_bounds__(256)
void bias_kernel(const float* __restrict__ rel_tab, float* __restrict__ tab)
{
    const int cls = blockIdx.x >> 4;
    const int h   = blockIdx.x & 15;
    const int whE = (cls >> 1) & 1;
    const int wwE = cls & 1;
    float* dst = tab + (size_t)blockIdx.x * NTOK * NTOK;
    for (int e = threadIdx.x; e < NTOK * NTOK; e += 256) {
        int i = e / NTOK, j = e % NTOK;
        int ih = i / 7, iw = i % 7, jh = j / 7, jw = j % 7;
        int ridx = (ih - jh + 6) * 13 + (iw - jw + 6);
        float s = rel_tab[ridx * NH_ + h];
        int li = (whE ? ((ih < 4) ? 1 : 2) : 0) * 3 + (wwE ? ((iw < 4) ? 1 : 2) : 0);
        int lj = (whE ? ((jh < 4) ? 1 : 2) : 0) * 3 + (wwE ? ((jw < 4) ? 1 : 2) : 0);
        if (li != lj) s -= 100.0f;
        dst[e] = s;
    }
}

// ---------------- LayerNorm (fp32 in -> fp16 out) -----------------------------
template <int MODE>
__global__ __launch_bounds__(128)
void ln_kernel(const float* __restrict__ src, const float* __restrict__ g,
               const float* __restrict__ b, __half* __restrict__ dst)
{
    const int m = blockIdx.x;
    const float* row;
    if (MODE == 1) {
        int r  = m / NTOK, nt = m % NTOK;
        int bb = r >> 6,   wi = r & 63;
        int wh = wi >> 3,  ww = wi & 7;
        int ih = nt / 7,   iw = nt % 7;
        int hs = wh * 7 + ih + SS_; if (hs >= HH)  hs -= HH;
        int ws = ww * 7 + iw + SS_; if (ws >= WW_) ws -= WW_;
        row = src + ((size_t)bb * 3136 + hs * 56 + ws) * 512;
    } else {
        row = src + (size_t)m * 512;
    }
    const int t = threadIdx.x;
    float4 v = *(const float4*)(row + t * 4);
    float s = v.x + v.y + v.z + v.w;
    float q = v.x * v.x + v.y * v.y + v.z * v.z + v.w * v.w;
    #pragma unroll
    for (int o = 16; o; o >>= 1) {
        s += __shfl_xor_sync(0xffffffffu, s, o);
        q += __shfl_xor_sync(0xffffffffu, q, o);
    }
    __shared__ float red[8];
    int warp = t >> 5, lane = t & 31;
    if (lane == 0) { red[warp] = s; red[warp + 4] = q; }
    __syncthreads();
    s = red[0] + red[1] + red[2] + red[3];
    q = red[4] + red[5] + red[6] + red[7];
    float mean = s * (1.0f / 512.0f);
    float var  = q * (1.0f / 512.0f) - mean * mean;
    float rstd = rsqrtf(var + 1e-5f);
    float4 gv = *(const float4*)(g + t * 4);
    float4 bv = *(const float4*)(b + t * 4);
    *(__half2*)(dst + (size_t)m * 512 + t * 4) =
        __floats2half2_rn((v.x - mean) * rstd * gv.x + bv.x,
                          (v.y - mean) * rstd * gv.y + bv.y);
    *(__half2*)(dst + (size_t)m * 512 + t * 4 + 2) =
        __floats2half2_rn((v.z - mean) * rstd * gv.z + bv.z,
                          (v.w - mean) * rstd * gv.w + bv.w);
}

// ---------------- fp16 TC GEMM: 128x128, 8 warps, 5 slots, paired stages ------
enum { EPI_NONE = 0, EPI_GELU = 1, EPI_SCATTER = 2, EPI_RES = 3 };

#define LDTH 40                         // pitch in halves (80B)
#define ASZH (128 * LDTH)               // halves per matrix per stage
#define STG_BYTES (2 * ASZH * 2)        // A+B per stage (20480 B)
#define NSTG 5
#define SMEM_BYTES (NSTG * STG_BYTES)   // 102400 B

__device__ __forceinline__ void mma16(float* c, const uint32_t* a, uint32_t b0, uint32_t b1) {
    asm volatile(
        "mma.sync.aligned.m16n8k16.row.col.f32.f16.f16.f32 "
        "{%0,%1,%2,%3},{%4,%5,%6,%7},{%8,%9},{%0,%1,%2,%3};\n"
        : "+f"(c[0]), "+f"(c[1]), "+f"(c[2]), "+f"(c[3])
        : "r"(a[0]), "r"(a[1]), "r"(a[2]), "r"(a[3]), "r"(b0), "r"(b1));
}
__device__ __forceinline__ void ldsm4(uint32_t* r, uint32_t addr) {
    asm volatile("ldmatrix.sync.aligned.m8n8.x4.shared.b16 {%0,%1,%2,%3}, [%4];"
        : "=r"(r[0]), "=r"(r[1]), "=r"(r[2]), "=r"(r[3]) : "r"(addr));
}
__device__ __forceinline__ void cp16(uint32_t dst, const void* src) {
    asm volatile("cp.async.cg.shared.global [%0], [%1], 16;\n" :: "r"(dst), "l"(src));
}
__device__ __forceinline__ void cp_commit() { asm volatile("cp.async.commit_group;\n"); }
__device__ __forceinline__ void cp_waitg1() { asm volatile("cp.async.wait_group 1;\n"); }

__device__ __forceinline__ size_t scatter_row(int m) {
    int r  = m / NTOK, nt = m % NTOK;
    int bb = r >> 6,   wi = r & 63;
    int wh = wi >> 3,  ww = wi & 7;
    int ih = nt / 7,   iw = nt % 7;
    int h = wh * 7 + ih + SS_; if (h >= HH)  h -= HH;
    int w = ww * 7 + iw + SS_; if (w >= WW_) w -= WW_;
    return (size_t)bb * 3136 + h * 56 + w;
}

// A [M,K] fp16 row-major, B [N,K] fp16 row-major; C = A @ B^T + bias.
// niter (= K/32) must be even (K = 512 or 2048 here).
template <int EPI>
__global__ __launch_bounds__(256, 2)
void gemm_tc(const __half* __restrict__ A, const __half* __restrict__ Bw,
             const float* __restrict__ bias, void* __restrict__ Cv,
             const float* __restrict__ res, int M, int N, int K)
{
    extern __shared__ __half sm[];
    const int tid  = threadIdx.x;
    const int lane = tid & 31, warp = tid >> 5;
    const int wm = warp & 1, wn = warp >> 1;          // 2x4 warps, warp tile 64x32
    const int m0 = blockIdx.y * 128, n0 = blockIdx.x * 128;

    float acc[4][4][4];
    #pragma unroll
    for (int i = 0; i < 4; i++)
        #pragma unroll
        for (int j = 0; j < 4; j++)
            #pragma unroll
            for (int t = 0; t < 4; t++) acc[i][j][t] = 0.0f;

    const int ldRow = tid >> 1;
    const int ldCol = (tid & 1) * 16;
    const __half* aSrc = A  + (size_t)(m0 + ldRow) * K + ldCol;
    const __half* bSrc = Bw + (size_t)(n0 + ldRow) * K + ldCol;
    const uint32_t smBase = (uint32_t)__cvta_generic_to_shared(sm);
    const uint32_t aDst = smBase + (uint32_t)(ldRow * LDTH + ldCol) * 2;
    const uint32_t bDst = aDst + ASZH * 2;

    const int niter = K >> 5;   // BK = 32, even

    // prologue: stages 0,1,2 -> slots 0,1,2 (3 commit groups)
    #pragma unroll
    for (int s = 0; s < 3; s++) {
        const __half* as = aSrc + s * 32;
        const __half* bs = bSrc + s * 32;
        const uint32_t off = s * STG_BYTES;
        cp16(aDst + off,      as);
        cp16(aDst + off + 16, as + 8);
        cp16(bDst + off,      bs);
        cp16(bDst + off + 16, bs + 8);
        cp_commit();
    }

    const int lrow  = lane & 15;
    const int lcol8 = (lane >> 4) * 8;
    const uint32_t aLd = smBase + (uint32_t)((wm * 64 + lrow) * LDTH + lcol8) * 2;
    const uint32_t bLd = smBase + ASZH * 2 + (uint32_t)((wn * 32 + lrow) * LDTH + lcol8) * 2;

    int s0 = 0;   // slot of stage `it` (it % 5)
    for (int it = 0; it < niter; it += 2) {
        // stages it, it+1 are the oldest 2 of <=3 pending groups
        cp_waitg1();
        __syncthreads();

        // prefetch stages it+3, it+4 into slots (s0+3)%5, (s0+4)%5
        // (those slots held stages it-2, it-1: computed last iteration, synced since)
        #pragma unroll
        for (int pf = 3; pf <= 4; pf++) {
            if (it + pf < niter) {
                int slot = s0 + pf; if (slot >= NSTG) slot -= NSTG;
                const __half* as = aSrc + (it + pf) * 32;
                const __half* bs = bSrc + (it + pf) * 32;
                const uint32_t off = slot * STG_BYTES;
                cp16(aDst + off,      as);
                cp16(aDst + off + 16, as + 8);
                cp16(bDst + off,      bs);
                cp16(bDst + off + 16, bs + 8);
            }
            cp_commit();
        }

        // compute stages it (slot s0) and it+1 (slot s0+1)
        #pragma unroll
        for (int st = 0; st < 2; st++) {
            int slot = s0 + st; if (slot >= NSTG) slot -= NSTG;
            const uint32_t so = slot * STG_BYTES;
            #pragma unroll
            for (int kk = 0; kk < 32; kk += 16) {
                uint32_t af[4][4], bq[2][4];
                #pragma unroll
                for (int im = 0; im < 4; im++)
                    ldsm4(af[im], aLd + so + (uint32_t)(im * 16 * LDTH + kk) * 2);
                #pragma unroll
                for (int p = 0; p < 2; p++)
                    ldsm4(bq[p], bLd + so + (uint32_t)(p * 16 * LDTH + kk) * 2);
                #pragma unroll
                for (int im = 0; im < 4; im++)
                    #pragma unroll
                    for (int jn = 0; jn < 4; jn++)
                        mma16(acc[im][jn], af[im], bq[jn >> 1][jn & 1], bq[jn >> 1][2 + (jn & 1)]);
            }
        }
        s0 += 2; if (s0 >= NSTG) s0 -= NSTG;
    }

    const int row = lane >> 2, col = lane & 3;
    #pragma unroll
    for (int im = 0; im < 4; im++) {
        const int r0 = m0 + wm * 64 + im * 16 + row;
        const int r1 = r0 + 8;
        size_t o0, o1;
        if (EPI == EPI_SCATTER) { o0 = scatter_row(r0); o1 = scatter_row(r1); }
        else                    { o0 = (size_t)r0;      o1 = (size_t)r1; }
        #pragma unroll
        for (int jn = 0; jn < 4; jn++) {
            const int n = n0 + wn * 32 + jn * 8 + 2 * col;
            const float b0 = bias[n], b1 = bias[n + 1];
            float v0 = acc[im][jn][0] + b0, v1 = acc[im][jn][1] + b1;
            float v2 = acc[im][jn][2] + b0, v3 = acc[im][jn][3] + b1;
            if (EPI == EPI_GELU) {
                v0 = 0.5f * v0 * (1.0f + erff(v0 * 0.70710678118654752f));
                v1 = 0.5f * v1 * (1.0f + erff(v1 * 0.70710678118654752f));
                v2 = 0.5f * v2 * (1.0f + erff(v2 * 0.70710678118654752f));
                v3 = 0.5f * v3 * (1.0f + erff(v3 * 0.70710678118654752f));
            }
            if (EPI == EPI_NONE || EPI == EPI_GELU) {
                __half* C = (__half*)Cv;
                *(__half2*)(C + o0 * N + n) = __floats2half2_rn(v0, v1);
                *(__half2*)(C + o1 * N + n) = __floats2half2_rn(v2, v3);
            } else {
                float* C = (float*)Cv;
                v0 += res[o0 * N + n]; v1 += res[o0 * N + n + 1];
                v2 += res[o1 * N + n]; v3 += res[o1 * N + n + 1];
                *(float2*)(C + o0 * N + n) = make_float2(v0, v1);
                *(float2*)(C + o1 * N + n) = make_float2(v2, v3);
            }
        }
    }
}

// ---------------- Windowed attention: tensor-core version ---------------------
#define QK_P 40
#define PV_P 72
#define S_P  66

__global__ __launch_bounds__(128)
void attn_kernel(const __half* __restrict__ qkv, const float* __restrict__ biasM,
                 __half* __restrict__ out)
{
    __shared__ __half Qs[64 * QK_P];
    __shared__ __half Ks[64 * QK_P];
    __shared__ __half Vt[32 * PV_P];
    __shared__ __half Ps[64 * PV_P];
    __shared__ float  S [64 * S_P];

    const int bi = blockIdx.x;
    const int h  = bi & 15;
    const int r  = bi >> 4;
    const int wi = r & 63;
    const int tid = threadIdx.x;
    const int lane = tid & 31, warp = tid >> 5;

    {
        int4* vz = (int4*)Vt;
        for (int i = tid; i < 32 * PV_P / 8; i += 128) vz[i] = make_int4(0, 0, 0, 0);
        int4* pz = (int4*)Ps;
        for (int i = tid; i < 64 * PV_P / 8; i += 128) pz[i] = make_int4(0, 0, 0, 0);
        int4* qz = (int4*)(Qs + 48 * QK_P);
        for (int i = tid; i < 16 * QK_P / 8; i += 128) qz[i] = make_int4(0, 0, 0, 0);
        int4* kz = (int4*)(Ks + 48 * QK_P);
        for (int i = tid; i < 16 * QK_P / 8; i += 128) kz[i] = make_int4(0, 0, 0, 0);
    }
    __syncthreads();

    const __half* base = qkv + (size_t)r * NTOK * 1536 + h * 32;
    for (int e = tid; e < NTOK * 16; e += 128) {
        int n = e >> 4, d2 = (e & 15) * 2;
        __half2 q2 = *(const __half2*)(base + n * 1536 + d2);
        __half2 k2 = *(const __half2*)(base + n * 1536 + 512 + d2);
        __half2 v2 = *(const __half2*)(base + n * 1536 + 1024 + d2);
        *(__half2*)(Qs + n * QK_P + d2) = q2;
        *(__half2*)(Ks + n * QK_P + d2) = k2;
        Vt[d2 * PV_P + n]       = __low2half(v2);
        Vt[(d2 + 1) * PV_P + n] = __high2half(v2);
    }
    __syncthreads();

    const uint32_t qBase = (uint32_t)__cvta_generic_to_shared(Qs);
    const uint32_t kBase = (uint32_t)__cvta_generic_to_shared(Ks);
    const uint32_t pBase = (uint32_t)__cvta_generic_to_shared(Ps);
    const uint32_t vBase = (uint32_t)__cvta_generic_to_shared(Vt);
    const int lrow  = lane & 15;
    const int lcol8 = (lane >> 4) * 8;

    // ---- S = Q @ K^T ----
    {
        float acc[8][4];
        #pragma unroll
        for (int j = 0; j < 8; j++)
            #pragma unroll
            for (int t = 0; t < 4; t++) acc[j][t] = 0.0f;

        #pragma unroll
        for (int kk = 0; kk < 32; kk += 16) {
            uint32_t af[4], bf[4][4];
            ldsm4(af, qBase + (uint32_t)((warp * 16 + lrow) * QK_P + lcol8 + kk) * 2);
            #pragma unroll
            for (int p = 0; p < 4; p++)
                ldsm4(bf[p], kBase + (uint32_t)((p * 16 + lrow) * QK_P + lcol8 + kk) * 2);
            #pragma unroll
            for (int jn = 0; jn < 8; jn++)
                mma16(acc[jn], af, bf[jn >> 1][jn & 1], bf[jn >> 1][2 + (jn & 1)]);
        }
        const int row0 = warp * 16 + (lane >> 2);
        const int c2 = (lane & 3) * 2;
        #pragma unroll
        for (int jn = 0; jn < 8; jn++) {
            const int cc = jn * 8 + c2;
            *(float2*)(S + row0 * S_P + cc) =
                make_float2(acc[jn][0] * SCALE_, acc[jn][1] * SCALE_);
            *(float2*)(S + (row0 + 8) * S_P + cc) =
                make_float2(acc[jn][2] * SCALE_, acc[jn][3] * SCALE_);
        }
    }
    __syncthreads();

    // ---- add precomputed bias+mask ----
    const int cls = (((wi >> 3) == 7) ? 2 : 0) + (((wi & 7) == 7) ? 1 : 0);
    const float* tab = biasM + (size_t)(cls * 16 + h) * NTOK * NTOK;
    for (int e = tid; e < NTOK * NTOK; e += 128) {
        int i = e / NTOK, j = e - i * NTOK;
        S[i * S_P + j] += tab[e];
    }
    __syncthreads();

    // ---- softmax, write fp16 P ----
    for (int i = warp; i < NTOK; i += 4) {
        float mx = -1e30f;
        for (int j = lane; j < NTOK; j += 32) mx = fmaxf(mx, S[i * S_P + j]);
        #pragma unroll
        for (int o = 16; o; o >>= 1) mx = fmaxf(mx, __shfl_xor_sync(0xffffffffu, mx, o));
        float sum = 0.0f;
        for (int j = lane; j < NTOK; j += 32) {
            float p = expf(S[i * S_P + j] - mx);
            S[i * S_P + j] = p;
            sum += p;
        }
        #pragma unroll
        for (int o = 16; o; o >>= 1) sum += __shfl_xor_sync(0xffffffffu, sum, o);
        float inv = 1.0f / sum;
        for (int j = lane; j < NTOK; j += 32)
            Ps[i * PV_P + j] = __float2half_rn(S[i * S_P + j] * inv);
    }
    __syncthreads();

    // ---- O = P @ V ----
    {
        float acc[4][4];
        #pragma unroll
        for (int j = 0; j < 4; j++)
            #pragma unroll
            for (int t = 0; t < 4; t++) acc[j][t] = 0.0f;

        #pragma unroll
        for (int kk = 0; kk < 64; kk += 16) {
            uint32_t af[4], bf[2][4];
            ldsm4(af, pBase + (uint32_t)((warp * 16 + lrow) * PV_P + lcol8 + kk) * 2);
            #pragma unroll
            for (int p = 0; p < 2; p++)
                ldsm4(bf[p], vBase + (uint32_t)((p * 16 + lrow) * PV_P + lcol8 + kk) * 2);
            #pragma unroll
            for (int jn = 0; jn < 4; jn++)
                mma16(acc[jn], af, bf[jn >> 1][jn & 1], bf[jn >> 1][2 + (jn & 1)]);
        }

        __half* obase = out + (size_t)r * NTOK * 512 + h * 32;
        const int row0 = warp * 16 + (lane >> 2);
        const int c2 = (lane & 3) * 2;
        #pragma unroll
        for (int jn = 0; jn < 4; jn++) {
            const int d = jn * 8 + c2;
            if (row0 < NTOK)
                *(__half2*)(obase + row0 * 512 + d) = __floats2half2_rn(acc[jn][0], acc[jn][1]);
            if (row0 + 8 < NTOK)
                *(__half2*)(obase + (row0 + 8) * 512 + d) = __floats2half2_rn(acc[jn][2], acc[jn][3]);
        }
    }
}

// ---------------- launcher ----------------------------------------------------
extern "C" void kernel_launch(void* const* d_in, const int* in_sizes, int n_in,
                              void* d_out, int out_size)
{
    const float* x1      = (const float*)d_in[0];
    const float* norm1_g = (const float*)d_in[2];
    const float* norm1_b = (const float*)d_in[3];
    const float* qkv_w   = (const float*)d_in[4];
    const float* qkv_b   = (const float*)d_in[5];
    const float* rel_tab = (const float*)d_in[6];
    const float* proj_w  = (const float*)d_in[7];
    const float* proj_b  = (const float*)d_in[8];
    const float* norm2_g = (const float*)d_in[9];
    const float* norm2_b = (const float*)d_in[10];
    const float* fc1_w   = (const float*)d_in[11];
    const float* fc1_b   = (const float*)d_in[12];
    const float* fc2_w   = (const float*)d_in[13];
    const float* fc2_b   = (const float*)d_in[14];

    __half *a1w, *qkvb, *attnb, *ln2b, *h1b, *wq, *wp, *w1, *w2;
    float *xb, *biasM;
    cudaGetSymbolAddress((void**)&a1w,   g_a1w);
    cudaGetSymbolAddress((void**)&qkvb,  g_qkv);
    cudaGetSymbolAddress((void**)&attnb, g_attn);
    cudaGetSymbolAddress((void**)&xb,    g_x);
    cudaGetSymbolAddress((void**)&ln2b,  g_ln2);
    cudaGetSymbolAddress((void**)&h1b,   g_h1);
    cudaGetSymbolAddress((void**)&wq,    g_wq);
    cudaGetSymbolAddress((void**)&wp,    g_wp);
    cudaGetSymbolAddress((void**)&w1,    g_w1);
    cudaGetSymbolAddress((void**)&w2,    g_w2);
    cudaGetSymbolAddress((void**)&biasM, g_bias);

    cudaFuncSetAttribute(gemm_tc<EPI_NONE>,    cudaFuncAttributeMaxDynamicSharedMemorySize, SMEM_BYTES);
    cudaFuncSetAttribute(gemm_tc<EPI_GELU>,    cudaFuncAttributeMaxDynamicSharedMemorySize, SMEM_BYTES);
    cudaFuncSetAttribute(gemm_tc<EPI_SCATTER>, cudaFuncAttributeMaxDynamicSharedMemorySize, SMEM_BYTES);
    cudaFuncSetAttribute(gemm_tc<EPI_RES>,     cudaFuncAttributeMaxDynamicSharedMemorySize, SMEM_BYTES);

    // 0) convert weights to fp16; precompute bias+mask table
    round_kernel<<<(1536 * 512) / 1024, 256>>>(qkv_w, wq, 1536 * 512);
    round_kernel<<<(512  * 512) / 1024, 256>>>(proj_w, wp, 512 * 512);
    round_kernel<<<(2048 * 512) / 1024, 256>>>(fc1_w, w1, 2048 * 512);
    round_kernel<<<(512 * 2048) / 1024, 256>>>(fc2_w, w2, 512 * 2048);
    bias_kernel<<<64, 256>>>(rel_tab, biasM);

    // 1) LN1 + roll + partition (fp16 out)
    ln_kernel<1><<<MROWS, 128>>>(x1, norm1_g, norm1_b, a1w);

    // 2) QKV projection
    {
        dim3 grid(1536 / 128, MROWS / 128);
        gemm_tc<EPI_NONE><<<grid, 256, SMEM_BYTES>>>(a1w, wq, qkv_b, qkvb, nullptr,
                                                     MROWS, 1536, 512);
    }

    // 3) windowed attention (tensor-core)
    attn_kernel<<<B_ * NWIN * NH_, 128>>>(qkvb, biasM, attnb);

    // 4) proj + reverse + roll + residual (fp32 out)
    {
        dim3 grid(512 / 128, MROWS / 128);
        gemm_tc<EPI_SCATTER><<<grid, 256, SMEM_BYTES>>>(attnb, wp, proj_b, xb, x1,
                                                        MROWS, 512, 512);
    }

    // 5) LN2 (fp16 out)
    ln_kernel<0><<<MROWS, 128>>>(xb, norm2_g, norm2_b, ln2b);

    // 6) fc1 + exact GELU (fp16 out)
    {
        dim3 grid(2048 / 128, MROWS / 128);
        gemm_tc<EPI_GELU><<<grid, 256, SMEM_BYTES>>>(ln2b, w1, fc1_b, h1b, nullptr,
                                                     MROWS, 2048, 512);
    }

    // 7) fc2 + residual -> out (fp32)
    {
        dim3 grid(512 / 128, MROWS / 128);
        gemm_tc<EPI_RES><<<grid, 256, SMEM_BYTES>>>(h1b, w2, fc2_b, d_out, xb,
                                                    MROWS, 512, 2048);
    }
}

// round 17
// speedup vs baseline: 1.1070x; 1.1070x over previous
#include <cuda_runtime.h>
#include <cuda_fp16.h>
#include <math.h>
#include <stdint.h>

// Problem constants
#define B_    16
#define HH    56
#define WW_   56
#define C_    512
#define NH_   16
#define WS_   7
#define SS_   3
#define NTOK  49
#define NWIN  64
#define HD_   32
#define MLPH  2048
#define MROWS 50176
#define SCALE_ 0.17677669529663687f

// ---------------- scratch ----------------------------------------------------
__device__ __half g_a1w [(size_t)MROWS * 512];
__device__ __half g_qkv [(size_t)MROWS * 1536];
__device__ __half g_attn[(size_t)MROWS * 512];
__device__ float  g_x   [(size_t)MROWS * 512];
__device__ __half g_ln2 [(size_t)MROWS * 512];
__device__ __half g_h1  [(size_t)MROWS * 2048];
__device__ __half g_wq [1536 * 512];
__device__ __half g_wp [512 * 512];
__device__ __half g_w1 [2048 * 512];
__device__ __half g_w2 [512 * 2048];
__device__ float  g_bias[4 * 16 * NTOK * NTOK];   // precomputed bias+mask per class/head

// one kernel converts all four weight matrices fp32 -> fp16
#define NWQ (1536 * 512)
#define NWP (512 * 512)
#define NW1 (2048 * 512)
#define NW2 (512 * 2048)
#define NW_TOT (NWQ + NWP + NW1 + NW2)

__global__ __launch_bounds__(256)
void round_all_kernel(const float* __restrict__ qkv_w, const float* __restrict__ proj_w,
                      const float* __restrict__ fc1_w, const float* __restrict__ fc2_w,
                      __half* __restrict__ wq, __half* __restrict__ wp,
                      __half* __restrict__ w1, __half* __restrict__ w2)
{
    int i = blockIdx.x * 1024 + threadIdx.x * 4;
    if (i >= NW_TOT) return;
    const float* src; __half* dst; int off;
    if (i < NWQ)                    { src = qkv_w;  dst = wq; off = i; }
    else if (i < NWQ + NWP)         { src = proj_w; dst = wp; off = i - NWQ; }
    else if (i < NWQ + NWP + NW1)   { src = fc1_w;  dst = w1; off = i - NWQ - NWP; }
    else                            { src = fc2_w;  dst = w2; off = i - NWQ - NWP - NW1; }
    float4 v = *(const float4*)(src + off);
    *(__half2*)(dst + off)     = __floats2half2_rn(v.x, v.y);
    *(__half2*)(dst + off + 2) = __floats2half2_rn(v.z, v.w);
}

// precompute bias + shifted-window mask: blockIdx.x = cls*16 + h
__global__ __launch_bounds__(256)
void bias_kernel(const float* __restrict__ rel_tab, float* __restrict__ tab)
{
    const int cls = blockIdx.x >> 4;
    const int h   = blockIdx.x & 15;
    const int whE = (cls >> 1) & 1;
    const int wwE = cls & 1;
    float* dst = tab + (size_t)blockIdx.x * NTOK * NTOK;
    for (int e = threadIdx.x; e < NTOK * NTOK; e += 256) {
        int i = e / NTOK, j = e % NTOK;
        int ih = i / 7, iw = i % 7, jh = j / 7, jw = j % 7;
        int ridx = (ih - jh + 6) * 13 + (iw - jw + 6);
        float s = rel_tab[ridx * NH_ + h];
        int li = (whE ? ((ih < 4) ? 1 : 2) : 0) * 3 + (wwE ? ((iw < 4) ? 1 : 2) : 0);
        int lj = (whE ? ((jh < 4) ? 1 : 2) : 0) * 3 + (wwE ? ((jw < 4) ? 1 : 2) : 0);
        if (li != lj) s -= 100.0f;
        dst[e] = s;
    }
}

// ---------------- LayerNorm (fp32 in -> fp16 out) -----------------------------
template <int MODE>
__global__ __launch_bounds__(128)
void ln_kernel(const float* __restrict__ src, const float* __restrict__ g,
               const float* __restrict__ b, __half* __restrict__ dst)
{
    const int m = blockIdx.x;
    const float* row;
    if (MODE == 1) {
        int r  = m / NTOK, nt = m % NTOK;
        int bb = r >> 6,   wi = r & 63;
        int wh = wi >> 3,  ww = wi & 7;
        int ih = nt / 7,   iw = nt % 7;
        int hs = wh * 7 + ih + SS_; if (hs >= HH)  hs -= HH;
        int ws = ww * 7 + iw + SS_; if (ws >= WW_) ws -= WW_;
        row = src + ((size_t)bb * 3136 + hs * 56 + ws) * 512;
    } else {
        row = src + (size_t)m * 512;
    }
    const int t = threadIdx.x;
    float4 v = *(const float4*)(row + t * 4);
    float s = v.x + v.y + v.z + v.w;
    float q = v.x * v.x + v.y * v.y + v.z * v.z + v.w * v.w;
    #pragma unroll
    for (int o = 16; o; o >>= 1) {
        s += __shfl_xor_sync(0xffffffffu, s, o);
        q += __shfl_xor_sync(0xffffffffu, q, o);
    }
    __shared__ float red[8];
    int warp = t >> 5, lane = t & 31;
    if (lane == 0) { red[warp] = s; red[warp + 4] = q; }
    __syncthreads();
    s = red[0] + red[1] + red[2] + red[3];
    q = red[4] + red[5] + red[6] + red[7];
    float mean = s * (1.0f / 512.0f);
    float var  = q * (1.0f / 512.0f) - mean * mean;
    float rstd = rsqrtf(var + 1e-5f);
    float4 gv = *(const float4*)(g + t * 4);
    float4 bv = *(const float4*)(b + t * 4);
    *(__half2*)(dst + (size_t)m * 512 + t * 4) =
        __floats2half2_rn((v.x - mean) * rstd * gv.x + bv.x,
                          (v.y - mean) * rstd * gv.y + bv.y);
    *(__half2*)(dst + (size_t)m * 512 + t * 4 + 2) =
        __floats2half2_rn((v.z - mean) * rstd * gv.z + bv.z,
                          (v.w - mean) * rstd * gv.w + bv.w);
}

// ---------------- fp16 TC GEMM: 128x128, 8 warps x 64x32, 4 stages ------------
enum { EPI_NONE = 0, EPI_GELU = 1, EPI_SCATTER = 2, EPI_RES = 3 };

#define LDTH 40                         // pitch in halves (80B)
#define ASZH (128 * LDTH)               // halves per matrix per stage
#define STG_BYTES (2 * ASZH * 2)        // A+B per stage (20480 B)
#define NSTG 4
#define SMEM_BYTES (NSTG * STG_BYTES)

__device__ __forceinline__ void mma16(float* c, const uint32_t* a, uint32_t b0, uint32_t b1) {
    asm volatile(
        "mma.sync.aligned.m16n8k16.row.col.f32.f16.f16.f32 "
        "{%0,%1,%2,%3},{%4,%5,%6,%7},{%8,%9},{%0,%1,%2,%3};\n"
        : "+f"(c[0]), "+f"(c[1]), "+f"(c[2]), "+f"(c[3])
        : "r"(a[0]), "r"(a[1]), "r"(a[2]), "r"(a[3]), "r"(b0), "r"(b1));
}
__device__ __forceinline__ void ldsm4(uint32_t* r, uint32_t addr) {
    asm volatile("ldmatrix.sync.aligned.m8n8.x4.shared.b16 {%0,%1,%2,%3}, [%4];"
        : "=r"(r[0]), "=r"(r[1]), "=r"(r[2]), "=r"(r[3]) : "r"(addr));
}
__device__ __forceinline__ void cp16(uint32_t dst, const void* src) {
    asm volatile("cp.async.cg.shared.global [%0], [%1], 16;\n" :: "r"(dst), "l"(src));
}
__device__ __forceinline__ void cp_commit() { asm volatile("cp.async.commit_group;\n"); }
__device__ __forceinline__ void cp_wait2()  { asm volatile("cp.async.wait_group 2;\n"); }

__device__ __forceinline__ size_t scatter_row(int m) {
    int r  = m / NTOK, nt = m % NTOK;
    int bb = r >> 6,   wi = r & 63;
    int wh = wi >> 3,  ww = wi & 7;
    int ih = nt / 7,   iw = nt % 7;
    int h = wh * 7 + ih + SS_; if (h >= HH)  h -= HH;
    int w = ww * 7 + iw + SS_; if (w >= WW_) w -= WW_;
    return (size_t)bb * 3136 + h * 56 + w;
}

template <int EPI>
__global__ __launch_bounds__(256, 2)
void gemm_tc(const __half* __restrict__ A, const __half* __restrict__ Bw,
             const float* __restrict__ bias, void* __restrict__ Cv,
             const float* __restrict__ res, int M, int N, int K)
{
    extern __shared__ __half sm[];
    const int tid  = threadIdx.x;
    const int lane = tid & 31, warp = tid >> 5;
    const int wm = warp & 1, wn = warp >> 1;          // 2x4 warps, warp tile 64x32
    const int m0 = blockIdx.y * 128, n0 = blockIdx.x * 128;

    float acc[4][4][4];
    #pragma unroll
    for (int i = 0; i < 4; i++)
        #pragma unroll
        for (int j = 0; j < 4; j++)
            #pragma unroll
            for (int t = 0; t < 4; t++) acc[i][j][t] = 0.0f;

    const int ldRow = tid >> 1;
    const int ldCol = (tid & 1) * 16;
    const __half* aSrc = A  + (size_t)(m0 + ldRow) * K + ldCol;
    const __half* bSrc = Bw + (size_t)(n0 + ldRow) * K + ldCol;
    const uint32_t smBase = (uint32_t)__cvta_generic_to_shared(sm);
    const uint32_t aDst = smBase + (uint32_t)(ldRow * LDTH + ldCol) * 2;
    const uint32_t bDst = aDst + ASZH * 2;

    const int niter = K >> 5;   // BK = 32

    #pragma unroll
    for (int s = 0; s < 3; s++) {
        const __half* as = aSrc + s * 32;
        const __half* bs = bSrc + s * 32;
        const uint32_t off = s * STG_BYTES;
        cp16(aDst + off,      as);
        cp16(aDst + off + 16, as + 8);
        cp16(bDst + off,      bs);
        cp16(bDst + off + 16, bs + 8);
        cp_commit();
    }

    const int lrow  = lane & 15;
    const int lcol8 = (lane >> 4) * 8;
    const uint32_t aLd = smBase + (uint32_t)((wm * 64 + lrow) * LDTH + lcol8) * 2;
    const uint32_t bLd = smBase + ASZH * 2 + (uint32_t)((wn * 32 + lrow) * LDTH + lcol8) * 2;

    int buf = 0;
    for (int it = 0; it < niter; it++) {
        cp_wait2();
        __syncthreads();

        if (it + 3 < niter) {
            const int nb = (buf + 3 >= NSTG) ? buf + 3 - NSTG : buf + 3;
            const __half* as = aSrc + (it + 3) * 32;
            const __half* bs = bSrc + (it + 3) * 32;
            const uint32_t off = nb * STG_BYTES;
            cp16(aDst + off,      as);
            cp16(aDst + off + 16, as + 8);
            cp16(bDst + off,      bs);
            cp16(bDst + off + 16, bs + 8);
        }
        cp_commit();

        const uint32_t so = buf * STG_BYTES;
        #pragma unroll
        for (int kk = 0; kk < 32; kk += 16) {
            uint32_t af[4][4], bq[2][4];
            #pragma unroll
            for (int im = 0; im < 4; im++)
                ldsm4(af[im], aLd + so + (uint32_t)(im * 16 * LDTH + kk) * 2);
            #pragma unroll
            for (int p = 0; p < 2; p++)
                ldsm4(bq[p], bLd + so + (uint32_t)(p * 16 * LDTH + kk) * 2);
            #pragma unroll
            for (int im = 0; im < 4; im++)
                #pragma unroll
                for (int jn = 0; jn < 4; jn++)
                    mma16(acc[im][jn], af[im], bq[jn >> 1][jn & 1], bq[jn >> 1][2 + (jn & 1)]);
        }
        buf = (buf + 1 == NSTG) ? 0 : buf + 1;
    }

    const int row = lane >> 2, col = lane & 3;
    #pragma unroll
    for (int im = 0; im < 4; im++) {
        const int r0 = m0 + wm * 64 + im * 16 + row;
        const int r1 = r0 + 8;
        size_t o0, o1;
        if (EPI == EPI_SCATTER) { o0 = scatter_row(r0); o1 = scatter_row(r1); }
        else                    { o0 = (size_t)r0;      o1 = (size_t)r1; }
        #pragma unroll
        for (int jn = 0; jn < 4; jn++) {
            const int n = n0 + wn * 32 + jn * 8 + 2 * col;
            const float b0 = bias[n], b1 = bias[n + 1];
            float v0 = acc[im][jn][0] + b0, v1 = acc[im][jn][1] + b1;
            float v2 = acc[im][jn][2] + b0, v3 = acc[im][jn][3] + b1;
            if (EPI == EPI_GELU) {
                v0 = 0.5f * v0 * (1.0f + erff(v0 * 0.70710678118654752f));
                v1 = 0.5f * v1 * (1.0f + erff(v1 * 0.70710678118654752f));
                v2 = 0.5f * v2 * (1.0f + erff(v2 * 0.70710678118654752f));
                v3 = 0.5f * v3 * (1.0f + erff(v3 * 0.70710678118654752f));
            }
            if (EPI == EPI_NONE || EPI == EPI_GELU) {
                __half* C = (__half*)Cv;
                *(__half2*)(C + o0 * N + n) = __floats2half2_rn(v0, v1);
                *(__half2*)(C + o1 * N + n) = __floats2half2_rn(v2, v3);
            } else {
                float* C = (float*)Cv;
                v0 += res[o0 * N + n]; v1 += res[o0 * N + n + 1];
                v2 += res[o1 * N + n]; v3 += res[o1 * N + n + 1];
                *(float2*)(C + o0 * N + n) = make_float2(v0, v1);
                *(float2*)(C + o1 * N + n) = make_float2(v2, v3);
            }
        }
    }
}

// ---------------- Windowed attention: tensor-core, bias folded into QK --------
#define QK_P 40
#define PV_P 72
#define S_P  66

__global__ __launch_bounds__(128)
void attn_kernel(const __half* __restrict__ qkv, const float* __restrict__ biasM,
                 __half* __restrict__ out)
{
    __shared__ __half Qs[64 * QK_P];
    __shared__ __half Ks[64 * QK_P];
    __shared__ __half Vt[32 * PV_P];
    __shared__ __half Ps[64 * PV_P];
    __shared__ float  S [64 * S_P];

    const int bi = blockIdx.x;
    const int h  = bi & 15;
    const int r  = bi >> 4;
    const int wi = r & 63;
    const int tid = threadIdx.x;
    const int lane = tid & 31, warp = tid >> 5;

    {
        int4* vz = (int4*)Vt;
        for (int i = tid; i < 32 * PV_P / 8; i += 128) vz[i] = make_int4(0, 0, 0, 0);
        int4* pz = (int4*)Ps;
        for (int i = tid; i < 64 * PV_P / 8; i += 128) pz[i] = make_int4(0, 0, 0, 0);
        int4* qz = (int4*)(Qs + 48 * QK_P);
        for (int i = tid; i < 16 * QK_P / 8; i += 128) qz[i] = make_int4(0, 0, 0, 0);
        int4* kz = (int4*)(Ks + 48 * QK_P);
        for (int i = tid; i < 16 * QK_P / 8; i += 128) kz[i] = make_int4(0, 0, 0, 0);
    }
    __syncthreads();

    const __half* base = qkv + (size_t)r * NTOK * 1536 + h * 32;
    for (int e = tid; e < NTOK * 16; e += 128) {
        int n = e >> 4, d2 = (e & 15) * 2;
        __half2 q2 = *(const __half2*)(base + n * 1536 + d2);
        __half2 k2 = *(const __half2*)(base + n * 1536 + 512 + d2);
        __half2 v2 = *(const __half2*)(base + n * 1536 + 1024 + d2);
        *(__half2*)(Qs + n * QK_P + d2) = q2;
        *(__half2*)(Ks + n * QK_P + d2) = k2;
        Vt[d2 * PV_P + n]       = __low2half(v2);
        Vt[(d2 + 1) * PV_P + n] = __high2half(v2);
    }
    __syncthreads();

    const uint32_t qBase = (uint32_t)__cvta_generic_to_shared(Qs);
    const uint32_t kBase = (uint32_t)__cvta_generic_to_shared(Ks);
    const uint32_t pBase = (uint32_t)__cvta_generic_to_shared(Ps);
    const uint32_t vBase = (uint32_t)__cvta_generic_to_shared(Vt);
    const int lrow  = lane & 15;
    const int lcol8 = (lane >> 4) * 8;

    // precomputed bias table for this window's mask class + head
    const int cls = (((wi >> 3) == 7) ? 2 : 0) + (((wi & 7) == 7) ? 1 : 0);
    const float* tab = biasM + (size_t)(cls * 16 + h) * NTOK * NTOK;

    // ---- S = Q @ K^T  (bias+mask folded into store) ----
    {
        float acc[8][4];
        #pragma unroll
        for (int j = 0; j < 8; j++)
            #pragma unroll
            for (int t = 0; t < 4; t++) acc[j][t] = 0.0f;

        #pragma unroll
        for (int kk = 0; kk < 32; kk += 16) {
            uint32_t af[4], bf[4][4];
            ldsm4(af, qBase + (uint32_t)((warp * 16 + lrow) * QK_P + lcol8 + kk) * 2);
            #pragma unroll
            for (int p = 0; p < 4; p++)
                ldsm4(bf[p], kBase + (uint32_t)((p * 16 + lrow) * QK_P + lcol8 + kk) * 2);
            #pragma unroll
            for (int jn = 0; jn < 8; jn++)
                mma16(acc[jn], af, bf[jn >> 1][jn & 1], bf[jn >> 1][2 + (jn & 1)]);
        }
        const int row0 = warp * 16 + (lane >> 2);
        const int row1 = row0 + 8;
        const int c2 = (lane & 3) * 2;
        const bool r0ok = row0 < NTOK, r1ok = row1 < NTOK;
        #pragma unroll
        for (int jn = 0; jn < 8; jn++) {
            const int cc = jn * 8 + c2;
            const bool c0ok = cc < NTOK, c1ok = cc + 1 < NTOK;
            float s00 = acc[jn][0] * SCALE_, s01 = acc[jn][1] * SCALE_;
            float s10 = acc[jn][2] * SCALE_, s11 = acc[jn][3] * SCALE_;
            if (r0ok && c0ok) s00 += tab[row0 * NTOK + cc];
            if (r0ok && c1ok) s01 += tab[row0 * NTOK + cc + 1];
            if (r1ok && c0ok) s10 += tab[row1 * NTOK + cc];
            if (r1ok && c1ok) s11 += tab[row1 * NTOK + cc + 1];
            *(float2*)(S + row0 * S_P + cc) = make_float2(s00, s01);
            *(float2*)(S + row1 * S_P + cc) = make_float2(s10, s11);
        }
    }
    __syncthreads();

    // ---- softmax, write fp16 P ----
    for (int i = warp; i < NTOK; i += 4) {
        float mx = -1e30f;
        for (int j = lane; j < NTOK; j += 32) mx = fmaxf(mx, S[i * S_P + j]);
        #pragma unroll
        for (int o = 16; o; o >>= 1) mx = fmaxf(mx, __shfl_xor_sync(0xffffffffu, mx, o));
        float sum = 0.0f;
        for (int j = lane; j < NTOK; j += 32) {
            float p = expf(S[i * S_P + j] - mx);
            S[i * S_P + j] = p;
            sum += p;
        }
        #pragma unroll
        for (int o = 16; o; o >>= 1) sum += __shfl_xor_sync(0xffffffffu, sum, o);
        float inv = 1.0f / sum;
        for (int j = lane; j < NTOK; j += 32)
            Ps[i * PV_P + j] = __float2half_rn(S[i * S_P + j] * inv);
    }
    __syncthreads();

    // ---- O = P @ V ----
    {
        float acc[4][4];
        #pragma unroll
        for (int j = 0; j < 4; j++)
            #pragma unroll
            for (int t = 0; t < 4; t++) acc[j][t] = 0.0f;

        #pragma unroll
        for (int kk = 0; kk < 64; kk += 16) {
            uint32_t af[4], bf[2][4];
            ldsm4(af, pBase + (uint32_t)((warp * 16 + lrow) * PV_P + lcol8 + kk) * 2);
            #pragma unroll
            for (int p = 0; p < 2; p++)
                ldsm4(bf[p], vBase + (uint32_t)((p * 16 + lrow) * PV_P + lcol8 + kk) * 2);
            #pragma unroll
            for (int jn = 0; jn < 4; jn++)
                mma16(acc[jn], af, bf[jn >> 1][jn & 1], bf[jn >> 1][2 + (jn & 1)]);
        }

        __half* obase = out + (size_t)r * NTOK * 512 + h * 32;
        const int row0 = warp * 16 + (lane >> 2);
        const int c2 = (lane & 3) * 2;
        #pragma unroll
        for (int jn = 0; jn < 4; jn++) {
            const int d = jn * 8 + c2;
            if (row0 < NTOK)
                *(__half2*)(obase + row0 * 512 + d) = __floats2half2_rn(acc[jn][0], acc[jn][1]);
            if (row0 + 8 < NTOK)
                *(__half2*)(obase + (row0 + 8) * 512 + d) = __floats2half2_rn(acc[jn][2], acc[jn][3]);
        }
    }
}

// ---------------- launcher ----------------------------------------------------
extern "C" void kernel_launch(void* const* d_in, const int* in_sizes, int n_in,
                              void* d_out, int out_size)
{
    const float* x1      = (const float*)d_in[0];
    const float* norm1_g = (const float*)d_in[2];
    const float* norm1_b = (const float*)d_in[3];
    const float* qkv_w   = (const float*)d_in[4];
    const float* qkv_b   = (const float*)d_in[5];
    const float* rel_tab = (const float*)d_in[6];
    const float* proj_w  = (const float*)d_in[7];
    const float* proj_b  = (const float*)d_in[8];
    const float* norm2_g = (const float*)d_in[9];
    const float* norm2_b = (const float*)d_in[10];
    const float* fc1_w   = (const float*)d_in[11];
    const float* fc1_b   = (const float*)d_in[12];
    const float* fc2_w   = (const float*)d_in[13];
    const float* fc2_b   = (const float*)d_in[14];

    __half *a1w, *qkvb, *attnb, *ln2b, *h1b, *wq, *wp, *w1, *w2;
    float *xb, *biasM;
    cudaGetSymbolAddress((void**)&a1w,   g_a1w);
    cudaGetSymbolAddress((void**)&qkvb,  g_qkv);
    cudaGetSymbolAddress((void**)&attnb, g_attn);
    cudaGetSymbolAddress((void**)&xb,    g_x);
    cudaGetSymbolAddress((void**)&ln2b,  g_ln2);
    cudaGetSymbolAddress((void**)&h1b,   g_h1);
    cudaGetSymbolAddress((void**)&wq,    g_wq);
    cudaGetSymbolAddress((void**)&wp,    g_wp);
    cudaGetSymbolAddress((void**)&w1,    g_w1);
    cudaGetSymbolAddress((void**)&w2,    g_w2);
    cudaGetSymbolAddress((void**)&biasM, g_bias);

    cudaFuncSetAttribute(gemm_tc<EPI_NONE>,    cudaFuncAttributeMaxDynamicSharedMemorySize, SMEM_BYTES);
    cudaFuncSetAttribute(gemm_tc<EPI_GELU>,    cudaFuncAttributeMaxDynamicSharedMemorySize, SMEM_BYTES);
    cudaFuncSetAttribute(gemm_tc<EPI_SCATTER>, cudaFuncAttributeMaxDynamicSharedMemorySize, SMEM_BYTES);
    cudaFuncSetAttribute(gemm_tc<EPI_RES>,     cudaFuncAttributeMaxDynamicSharedMemorySize, SMEM_BYTES);

    // 0) convert all weights to fp16 (one launch); precompute bias+mask table
    round_all_kernel<<<(NW_TOT + 1023) / 1024, 256>>>(qkv_w, proj_w, fc1_w, fc2_w,
                                                      wq, wp, w1, w2);
    bias_kernel<<<64, 256>>>(rel_tab, biasM);

    // 1) LN1 + roll + partition (fp16 out)
    ln_kernel<1><<<MROWS, 128>>>(x1, norm1_g, norm1_b, a1w);

    // 2) QKV projection
    {
        dim3 grid(1536 / 128, MROWS / 128);
        gemm_tc<EPI_NONE><<<grid, 256, SMEM_BYTES>>>(a1w, wq, qkv_b, qkvb, nullptr,
                                                     MROWS, 1536, 512);
    }

    // 3) windowed attention (tensor-core, bias folded)
    attn_kernel<<<B_ * NWIN * NH_, 128>>>(qkvb, biasM, attnb);

    // 4) proj + reverse + roll + residual (fp32 out)
    {
        dim3 grid(512 / 128, MROWS / 128);
        gemm_tc<EPI_SCATTER><<<grid, 256, SMEM_BYTES>>>(attnb, wp, proj_b, xb, x1,
                                                        MROWS, 512, 512);
    }

    // 5) LN2 (fp16 out)
    ln_kernel<0><<<MROWS, 128>>>(xb, norm2_g, norm2_b, ln2b);

    // 6) fc1 + exact GELU (fp16 out)
    {
        dim3 grid(2048 / 128, MROWS / 128);
        gemm_tc<EPI_GELU><<<grid, 256, SMEM_BYTES>>>(ln2b, w1, fc1_b, h1b, nullptr,
                                                     MROWS, 2048, 512);
    }

    // 7) fc2 + residual -> out (fp32)
    {
        dim3 grid(512 / 128, MROWS / 128);
        gemm_tc<EPI_RES><<<grid, 256, SMEM_BYTES>>>(h1b, w2, fc2_b, d_out, xb,
                                                    MROWS, 512, 2048);
    }
}